// round 14
// baseline (speedup 1.0000x reference)
#include <cuda_runtime.h>
#include <math.h>
#include <stdint.h>

#define TB 8192        // B*T tokens
#define DM 1024
#define NH 16
#define HS 64
#define TT 2048
#define NE 8
#define HD 2730
#define HP 2732        // padded row stride for hidden
#define NSLOT 17408
#define LNEPS 1e-5f

// ---------------- scratch (R13 layout) ----------------
__device__ float g_xn[TB * DM];
__device__ float g_q[TB * DM];
__device__ float g_k[TB * DM];
__device__ float g_v[TB * DM];
__device__ float g_att[TB * DM];
__device__ float g_x1[TB * DM];
__device__ float g_wqkv[DM * 3 * DM];
__device__ int   g_eid[TB * 2];
__device__ float g_gate[TB * 2];
__device__ int   g_count[NE];
__device__ int   g_cursor[NE];
__device__ int   g_seg[NE + 1];
__device__ int   g_slot_tok[NSLOT];
__device__ int   g_tok_slot[TB * 2];
__device__ float g_xg[NSLOT * DM];
__device__ float g_h[(size_t)NSLOT * HP];
__device__ float g_y[NSLOT * DM];

// ---------------- init ----------------
__global__ void k_init() {
    if (threadIdx.x < NE) { g_count[threadIdx.x] = 0; g_cursor[threadIdx.x] = 0; }
}

// ---------------- pack per-head QKV weights into one [D, 3072] matrix ----------------
__global__ void k_pack(const float* __restrict__ wq, const float* __restrict__ wk,
                       const float* __restrict__ wv) {
    int i = blockIdx.x * 256 + threadIdx.x;
    const int per = NH * DM * HS;
    if (i >= 3 * per) return;
    int which = i / per;
    int r = i % per;
    int h = r >> 16;
    int r2 = r & 65535;
    int d = r2 >> 6;
    int s = r2 & 63;
    const float* src = (which == 0) ? wq : (which == 1) ? wk : wv;
    g_wqkv[(size_t)d * 3072 + h * 192 + which * 64 + s] = src[r];
}

// ---------------- layernorm ----------------
__global__ void k_ln(const float* __restrict__ xin, const float* __restrict__ gg,
                     const float* __restrict__ bb, int mode) {
    const float* src = mode ? g_x1 : xin;
    int row = blockIdx.x;
    const float* xr = src + (size_t)row * DM;
    int tid = threadIdx.x;
    float v[4]; float s = 0.f, s2 = 0.f;
#pragma unroll
    for (int i = 0; i < 4; i++) { v[i] = xr[tid + i * 256]; s += v[i]; s2 += v[i] * v[i]; }
#pragma unroll
    for (int o = 16; o; o >>= 1) {
        s  += __shfl_xor_sync(0xffffffffu, s, o);
        s2 += __shfl_xor_sync(0xffffffffu, s2, o);
    }
    __shared__ float ws[8], ws2[8], stat[2];
    int warp = tid >> 5, lane = tid & 31;
    if (lane == 0) { ws[warp] = s; ws2[warp] = s2; }
    __syncthreads();
    if (tid == 0) {
        float ts = 0.f, t2 = 0.f;
        for (int w = 0; w < 8; w++) { ts += ws[w]; t2 += ws2[w]; }
        float mu = ts * (1.f / DM);
        float var = t2 * (1.f / DM) - mu * mu;
        stat[0] = mu; stat[1] = rsqrtf(var + LNEPS);
    }
    __syncthreads();
    float mu = stat[0], inv = stat[1];
    float* outr = g_xn + (size_t)row * DM;
#pragma unroll
    for (int i = 0; i < 4; i++) {
        int c = tid + i * 256;
        outr[c] = (v[i] - mu) * inv * gg[c] + bb[c];
    }
}

// ---------------- FFMA GEMM core (R13 exact): conflict-free B fragments ------------
#define GEMM2_PROLOG \
    __shared__ float As[16][136]; \
    __shared__ float Bs[16][132]; \
    const int tx4 = (threadIdx.x & 15) * 4; \
    const int ty8 = (threadIdx.x >> 4) * 8; \
    float acc[8][8] = {}; \
    const int am = threadIdx.x >> 1, ak = (threadIdx.x & 1) * 8; \
    const int bk = threadIdx.x >> 4, bn0 = (threadIdx.x & 15) * 8; \
    float pra[8], prb[8];

#define GEMM2_LOAD(AEXPR, BEXPR) \
    { _Pragma("unroll") for (int u = 0; u < 8; ++u) { const int kk = k0 + ak + u; pra[u] = (AEXPR); } \
      { const int kk = k0 + bk; \
        _Pragma("unroll") for (int u = 0; u < 8; ++u) { const int nn = bn0 + u; prb[u] = (BEXPR); } } }

#define GEMM2_LOOP(KT, AEXPR, BEXPR) \
    int k0 = 0; \
    GEMM2_LOAD(AEXPR, BEXPR) \
    for (int kt = 0; kt < (KT); ++kt) { \
        __syncthreads(); \
        _Pragma("unroll") for (int u = 0; u < 8; ++u) As[ak + u][am] = pra[u]; \
        _Pragma("unroll") for (int u = 0; u < 8; ++u) Bs[bk][bn0 + u] = prb[u]; \
        __syncthreads(); \
        if (kt + 1 < (KT)) { k0 = (kt + 1) * 16; GEMM2_LOAD(AEXPR, BEXPR) } \
        _Pragma("unroll") \
        for (int k = 0; k < 16; ++k) { \
            float ra[8], rb[8]; \
            *(float4*)&ra[0] = *(const float4*)&As[k][ty8]; \
            *(float4*)&ra[4] = *(const float4*)&As[k][ty8 + 4]; \
            *(float4*)&rb[0] = *(const float4*)&Bs[k][tx4]; \
            *(float4*)&rb[4] = *(const float4*)&Bs[k][64 + tx4]; \
            _Pragma("unroll") for (int i = 0; i < 8; ++i) \
                _Pragma("unroll") for (int j = 0; j < 8; ++j) \
                    acc[i][j] = fmaf(ra[i], rb[j], acc[i][j]); \
        } \
    }

#define EPILOG(...) \
    _Pragma("unroll") for (int i = 0; i < 8; i++) { \
        const int m = row0 + ty8 + i; (void)m; \
        _Pragma("unroll") for (int j = 0; j < 8; j++) { \
            const int n = n0 + ((j < 4) ? (tx4 + j) : (60 + tx4 + j)); \
            const float v = acc[i][j]; \
            __VA_ARGS__ \
        } }

// QKV: [8192,1024] x [1024,3072] -> scatter q/k/v [B,H,T,HS]
__global__ __launch_bounds__(256, 2) void k_qkv() {
    const int row0 = blockIdx.y * 128;
    const int n0 = blockIdx.x * 128;
    GEMM2_PROLOG
    GEMM2_LOOP(64,
               g_xn[(size_t)(row0 + am) * DM + kk],
               g_wqkv[(size_t)kk * 3072 + n0 + nn])
    EPILOG({
        int b = m >> 11;
        int t = m & 2047;
        int hh = n / 192;
        int rr = n % 192;
        int w = rr >> 6;
        int s = rr & 63;
        float* dst = (w == 0) ? g_q : (w == 1) ? g_k : g_v;
        dst[(((size_t)(b * NH + hh)) * TT + t) * HS + s] = v;
    })
}

// out proj + bias + residual
__global__ __launch_bounds__(256, 2) void k_proj(const float* __restrict__ x,
                                                 const float* __restrict__ wo,
                                                 const float* __restrict__ bo) {
    const int row0 = blockIdx.y * 128;
    const int n0 = blockIdx.x * 128;
    GEMM2_PROLOG
    GEMM2_LOOP(64,
               g_att[(size_t)(row0 + am) * DM + kk],
               wo[(size_t)kk * DM + n0 + nn])
    EPILOG({
        g_x1[(size_t)m * DM + n] = v + bo[n] + x[(size_t)m * DM + n];
    })
}

// grouped MoE GEMM: mode 0 -> g_h = xg@w1[e]+b1 ; mode 1 -> g_h *= silu(xg@w2[e]+b2)
__global__ __launch_bounds__(256, 2) void k_moe1(const float* __restrict__ W,
                                                 const float* __restrict__ Bv, int mode) {
    const int row0 = blockIdx.y * 128;
    if (row0 >= g_seg[NE]) return;
    int e = 0;
    while (row0 >= g_seg[e + 1]) e++;
    const float* We = W + (size_t)e * DM * HD;
    const float* Be = Bv + (size_t)e * HD;
    const int n0 = blockIdx.x * 128;
    GEMM2_PROLOG
    GEMM2_LOOP(64,
               g_xg[(size_t)(row0 + am) * DM + kk],
               ((n0 + nn) < HD ? We[(size_t)kk * HD + n0 + nn] : 0.f))
    EPILOG({
        if (n < HD) {
            size_t idx = (size_t)m * HP + n;
            if (mode == 0) {
                g_h[idx] = v + Be[n];
            } else {
                float a = v + Be[n];
                g_h[idx] *= a / (1.f + __expf(-a));
            }
        }
    })
}

// grouped MoE GEMM 2: g_y = g_h @ w3[e] + b3[e]
__global__ __launch_bounds__(256, 2) void k_moe2(const float* __restrict__ W3,
                                                 const float* __restrict__ B3) {
    const int row0 = blockIdx.y * 128;
    if (row0 >= g_seg[NE]) return;
    int e = 0;
    while (row0 >= g_seg[e + 1]) e++;
    const float* We = W3 + (size_t)e * HD * DM;
    const float* Be = B3 + (size_t)e * DM;
    const int n0 = blockIdx.x * 128;
    GEMM2_PROLOG
    GEMM2_LOOP(171,
               (kk < HD ? g_h[(size_t)(row0 + am) * HP + kk] : 0.f),
               (kk < HD ? We[(size_t)kk * DM + n0 + nn] : 0.f))
    EPILOG({
        g_y[(size_t)m * DM + n] = v + Be[n];
    })
}

// ---------------- flash attention: vectorized q/p fragment loads + __expf ----------
__global__ void k_attn() {
    extern __shared__ float smf[];
    float(*qs)[68] = (float(*)[68])smf;
    float(*kp)[68] = (float(*)[68])(smf + 64 * 68);
    float(*vs)[68] = (float(*)[68])(smf + 2 * 64 * 68);
    const int qt = blockIdx.x, bh = blockIdx.y;
    const int tid = threadIdx.x;
    const int tx = tid & 15, ty = tid >> 4;
    const size_t base = (size_t)bh * TT * HS;
    const float* qg = g_q + base + (size_t)qt * 64 * HS;
    const float* kg = g_k + base;
    const float* vg = g_v + base;
    {
        int r = tid >> 2, d0 = (tid & 3) * 16;
#pragma unroll
        for (int u = 0; u < 16; u++) qs[r][d0 + u] = qg[r * HS + d0 + u] * 0.125f;
    }
    float acc[4][4] = {};
    float mr[4], lr[4];
#pragma unroll
    for (int i = 0; i < 4; i++) { mr[i] = -INFINITY; lr[i] = 0.f; }

    for (int kt = 0; kt <= qt; ++kt) {
        __syncthreads();
        {
            int r = tid >> 2, d0 = (tid & 3) * 16;
            const float* kk = kg + (size_t)(kt * 64 + r) * HS;
            const float* vv = vg + (size_t)(kt * 64 + r) * HS;
#pragma unroll
            for (int u = 0; u < 16; u++) {
                kp[d0 + u][r] = kk[d0 + u];
                vs[r][d0 + u] = vv[d0 + u];
            }
        }
        __syncthreads();
        float s[4][4] = {};
#pragma unroll 4
        for (int d4 = 0; d4 < 64; d4 += 4) {
            float4 q4[4];
#pragma unroll
            for (int ii = 0; ii < 4; ii++) q4[ii] = *(const float4*)&qs[ty * 4 + ii][d4];
#pragma unroll
            for (int dd = 0; dd < 4; dd++) {
                float4 k4 = *(const float4*)&kp[d4 + dd][tx * 4];
                float kv[4] = { k4.x, k4.y, k4.z, k4.w };
#pragma unroll
                for (int ii = 0; ii < 4; ii++) {
                    const float qd = (dd == 0) ? q4[ii].x : (dd == 1) ? q4[ii].y
                                    : (dd == 2) ? q4[ii].z : q4[ii].w;
#pragma unroll
                    for (int jj = 0; jj < 4; jj++)
                        s[ii][jj] = fmaf(qd, kv[jj], s[ii][jj]);
                }
            }
        }
        if (kt == qt) {
#pragma unroll
            for (int ii = 0; ii < 4; ii++)
#pragma unroll
                for (int jj = 0; jj < 4; jj++)
                    if (tx * 4 + jj > ty * 4 + ii) s[ii][jj] = -INFINITY;
        }
        float mn[4], cor[4];
#pragma unroll
        for (int ii = 0; ii < 4; ii++) {
            float mx = fmaxf(fmaxf(s[ii][0], s[ii][1]), fmaxf(s[ii][2], s[ii][3]));
#pragma unroll
            for (int o = 8; o; o >>= 1) mx = fmaxf(mx, __shfl_xor_sync(0xffffffffu, mx, o));
            mn[ii] = fmaxf(mr[ii], mx);
            cor[ii] = __expf(mr[ii] - mn[ii]);
            mr[ii] = mn[ii];
        }
#pragma unroll
        for (int ii = 0; ii < 4; ii++) {
            float su = 0.f;
#pragma unroll
            for (int jj = 0; jj < 4; jj++) { s[ii][jj] = __expf(s[ii][jj] - mn[ii]); su += s[ii][jj]; }
#pragma unroll
            for (int o = 8; o; o >>= 1) su += __shfl_xor_sync(0xffffffffu, su, o);
            lr[ii] = lr[ii] * cor[ii] + su;
#pragma unroll
            for (int jj = 0; jj < 4; jj++) acc[ii][jj] *= cor[ii];
        }
        __syncthreads();
#pragma unroll
        for (int ii = 0; ii < 4; ii++)
#pragma unroll
            for (int jj = 0; jj < 4; jj++) kp[ty * 4 + ii][tx * 4 + jj] = s[ii][jj];
        __syncthreads();
#pragma unroll 4
        for (int c4 = 0; c4 < 64; c4 += 4) {
            float4 p4[4];
#pragma unroll
            for (int ii = 0; ii < 4; ii++) p4[ii] = *(const float4*)&kp[ty * 4 + ii][c4];
#pragma unroll
            for (int cc = 0; cc < 4; cc++) {
                float4 v4 = *(const float4*)&vs[c4 + cc][tx * 4];
                float vv[4] = { v4.x, v4.y, v4.z, v4.w };
#pragma unroll
                for (int ii = 0; ii < 4; ii++) {
                    const float pv = (cc == 0) ? p4[ii].x : (cc == 1) ? p4[ii].y
                                    : (cc == 2) ? p4[ii].z : p4[ii].w;
#pragma unroll
                    for (int jj = 0; jj < 4; jj++)
                        acc[ii][jj] = fmaf(pv, vv[jj], acc[ii][jj]);
                }
            }
        }
    }
    int b = bh >> 4, h = bh & 15;
#pragma unroll
    for (int ii = 0; ii < 4; ii++) {
        float inv = 1.f / lr[ii];
#pragma unroll
        for (int jj = 0; jj < 4; jj++) {
            int row = qt * 64 + ty * 4 + ii;
            g_att[((size_t)(b * TT + row)) * DM + h * HS + tx * 4 + jj] = acc[ii][jj] * inv;
        }
    }
}

// ---------------- router / moe routing (R13 exact) ----------------
__global__ void k_router(const float* __restrict__ rw, const float* __restrict__ rb) {
    int t = blockIdx.x * 8 + (threadIdx.x >> 5);
    int lane = threadIdx.x & 31;
    const float* xr = g_xn + (size_t)t * DM;
    float a[NE] = {};
    for (int d = lane; d < DM; d += 32) {
        float xv = xr[d];
        const float* w = rw + (size_t)d * NE;
#pragma unroll
        for (int e = 0; e < NE; e++) a[e] += xv * w[e];
    }
#pragma unroll
    for (int e = 0; e < NE; e++)
#pragma unroll
        for (int o = 16; o; o >>= 1) a[e] += __shfl_xor_sync(0xffffffffu, a[e], o);
    if (lane == 0) {
#pragma unroll
        for (int e = 0; e < NE; e++) a[e] += rb[e];
        int e1 = 0; float v1 = a[0];
#pragma unroll
        for (int e = 1; e < NE; e++) if (a[e] > v1) { v1 = a[e]; e1 = e; }
        int e2 = -1; float v2 = -INFINITY;
#pragma unroll
        for (int e = 0; e < NE; e++) if (e != e1 && a[e] > v2) { v2 = a[e]; e2 = e; }
        float w2 = expf(v2 - v1);
        float inv = 1.f / (1.f + w2);
        g_eid[t * 2] = e1; g_eid[t * 2 + 1] = e2;
        g_gate[t * 2] = inv; g_gate[t * 2 + 1] = w2 * inv;
        atomicAdd(&g_count[e1], 1);
        atomicAdd(&g_count[e2], 1);
    }
}

__global__ void k_seg() {
    if (threadIdx.x == 0) {
        int s = 0; g_seg[0] = 0;
        for (int e = 0; e < NE; e++) { s += (g_count[e] + 127) & ~127; g_seg[e + 1] = s; }
    }
}

__global__ void k_fill() {
    int i = blockIdx.x * 256 + threadIdx.x;
    if (i < NSLOT) g_slot_tok[i] = -1;
}

__global__ void k_scatter() {
    int i = blockIdx.x * 256 + threadIdx.x;
    int t = i >> 1;
    int e = g_eid[i];
    int pos = atomicAdd(&g_cursor[e], 1);
    int slot = g_seg[e] + pos;
    g_slot_tok[slot] = t;
    g_tok_slot[i] = slot;
}

__global__ void k_gather() {
    int slot = blockIdx.x;
    int t = g_slot_tok[slot];
    float* dst = g_xg + (size_t)slot * DM;
    if (t >= 0) {
        const float* src = g_xn + (size_t)t * DM;
#pragma unroll
        for (int i = 0; i < 4; i++) dst[threadIdx.x + i * 256] = src[threadIdx.x + i * 256];
    } else {
#pragma unroll
        for (int i = 0; i < 4; i++) dst[threadIdx.x + i * 256] = 0.f;
    }
}

__global__ void k_combine(float* __restrict__ out) {
    int t = blockIdx.x;
    int s0 = g_tok_slot[t * 2], s1 = g_tok_slot[t * 2 + 1];
    float g0 = g_gate[t * 2], g1 = g_gate[t * 2 + 1];
    const float* y0 = g_y + (size_t)s0 * DM;
    const float* y1 = g_y + (size_t)s1 * DM;
    const float* xr = g_x1 + (size_t)t * DM;
    float* o = out + (size_t)t * DM;
#pragma unroll
    for (int i = 0; i < 4; i++) {
        int c = threadIdx.x + i * 256;
        o[c] = xr[c] + g0 * y0[c] + g1 * y1[c];
    }
}

// ---------------- launch (R13 exact sequence) ----------------
extern "C" void kernel_launch(void* const* d_in, const int* in_sizes, int n_in,
                              void* d_out, int out_size) {
    const float* x    = (const float*)d_in[0];
    const float* ln1g = (const float*)d_in[1];
    const float* ln1b = (const float*)d_in[2];
    const float* wq   = (const float*)d_in[3];
    const float* wk   = (const float*)d_in[4];
    const float* wv   = (const float*)d_in[5];
    const float* wo   = (const float*)d_in[6];
    const float* bo   = (const float*)d_in[7];
    const float* ln2g = (const float*)d_in[8];
    const float* ln2b = (const float*)d_in[9];
    const float* rw   = (const float*)d_in[10];
    const float* rb   = (const float*)d_in[11];
    const float* w1   = (const float*)d_in[12];
    const float* b1   = (const float*)d_in[13];
    const float* w2   = (const float*)d_in[14];
    const float* b2   = (const float*)d_in[15];
    const float* w3   = (const float*)d_in[16];
    const float* b3   = (const float*)d_in[17];
    float* out = (float*)d_out;

    const int attn_smem = 3 * 64 * 68 * (int)sizeof(float);
    cudaFuncSetAttribute(k_attn, cudaFuncAttributeMaxDynamicSharedMemorySize, attn_smem);

    k_init<<<1, 32>>>();
    k_pack<<<(3 * NH * DM * HS + 255) / 256, 256>>>(wq, wk, wv);
    k_ln<<<TB, 256>>>(x, ln1g, ln1b, 0);
    k_qkv<<<dim3(24, 64), 256>>>();
    k_attn<<<dim3(32, 64), 256, attn_smem>>>();
    k_proj<<<dim3(8, 64), 256>>>(x, wo, bo);
    k_ln<<<TB, 256>>>(x, ln2g, ln2b, 1);
    k_router<<<TB / 8, 256>>>(rw, rb);
    k_seg<<<1, 32>>>();
    k_fill<<<(NSLOT + 255) / 256, 256>>>();
    k_scatter<<<TB * 2 / 256, 256>>>();
    k_gather<<<NSLOT, 256>>>();
    k_moe1<<<dim3(22, NSLOT / 128), 256>>>(w1, b1, 0);
    k_moe1<<<dim3(22, NSLOT / 128), 256>>>(w2, b2, 1);
    k_moe2<<<dim3(8, NSLOT / 128), 256>>>(w3, b3);
    k_combine<<<TB, 256>>>(out);
}

// round 15
// speedup vs baseline: 1.0018x; 1.0018x over previous
#include <cuda_runtime.h>
#include <math.h>
#include <stdint.h>

#define TB 8192        // B*T tokens
#define DM 1024
#define NH 16
#define HS 64
#define TT 2048
#define NE 8
#define HD 2730
#define HP 2732        // padded row stride for hidden
#define NSLOT 17408
#define LNEPS 1e-5f

// ---------------- scratch ----------------
__device__ float g_xn[TB * DM];
__device__ float g_q[TB * DM];
__device__ float g_k[TB * DM];
__device__ float g_v[TB * DM];
__device__ float g_att[TB * DM];
__device__ float g_x1[TB * DM];
__device__ float g_wqkv[DM * 3 * DM];
__device__ int   g_eid[TB * 2];
__device__ float g_gate[TB * 2];
__device__ int   g_count[NE];
__device__ int   g_cursor[NE];
__device__ int   g_seg[NE + 1];
__device__ int   g_slot_tok[NSLOT];
__device__ int   g_tok_slot[TB * 2];
__device__ float g_xg[NSLOT * DM];
__device__ float g_h[(size_t)NSLOT * HP];
__device__ float g_y[NSLOT * DM];

// ---------------- init ----------------
__global__ void k_init() {
    if (threadIdx.x < NE) { g_count[threadIdx.x] = 0; g_cursor[threadIdx.x] = 0; }
}

// ---------------- pack per-head QKV weights into one [D, 3072] matrix ----------------
__global__ void k_pack(const float* __restrict__ wq, const float* __restrict__ wk,
                       const float* __restrict__ wv) {
    int i = blockIdx.x * 256 + threadIdx.x;
    const int per = NH * DM * HS;
    if (i >= 3 * per) return;
    int which = i / per;
    int r = i % per;
    int h = r >> 16;
    int r2 = r & 65535;
    int d = r2 >> 6;
    int s = r2 & 63;
    const float* src = (which == 0) ? wq : (which == 1) ? wk : wv;
    g_wqkv[(size_t)d * 3072 + h * 192 + which * 64 + s] = src[r];
}

// ---------------- layernorm ----------------
__global__ void k_ln(const float* __restrict__ xin, const float* __restrict__ gg,
                     const float* __restrict__ bb, int mode) {
    const float* src = mode ? g_x1 : xin;
    int row = blockIdx.x;
    const float* xr = src + (size_t)row * DM;
    int tid = threadIdx.x;
    float v[4]; float s = 0.f, s2 = 0.f;
#pragma unroll
    for (int i = 0; i < 4; i++) { v[i] = xr[tid + i * 256]; s += v[i]; s2 += v[i] * v[i]; }
#pragma unroll
    for (int o = 16; o; o >>= 1) {
        s  += __shfl_xor_sync(0xffffffffu, s, o);
        s2 += __shfl_xor_sync(0xffffffffu, s2, o);
    }
    __shared__ float ws[8], ws2[8], stat[2];
    int warp = tid >> 5, lane = tid & 31;
    if (lane == 0) { ws[warp] = s; ws2[warp] = s2; }
    __syncthreads();
    if (tid == 0) {
        float ts = 0.f, t2 = 0.f;
        for (int w = 0; w < 8; w++) { ts += ws[w]; t2 += ws2[w]; }
        float mu = ts * (1.f / DM);
        float var = t2 * (1.f / DM) - mu * mu;
        stat[0] = mu; stat[1] = rsqrtf(var + LNEPS);
    }
    __syncthreads();
    float mu = stat[0], inv = stat[1];
    float* outr = g_xn + (size_t)row * DM;
#pragma unroll
    for (int i = 0; i < 4; i++) {
        int c = tid + i * 256;
        outr[c] = (v[i] - mu) * inv * gg[c] + bb[c];
    }
}

// ---------------- FFMA GEMM core (R13 exact): conflict-free B fragments ------------
#define GEMM2_PROLOG \
    __shared__ float As[16][136]; \
    __shared__ float Bs[16][132]; \
    const int tx4 = (threadIdx.x & 15) * 4; \
    const int ty8 = (threadIdx.x >> 4) * 8; \
    float acc[8][8] = {}; \
    const int am = threadIdx.x >> 1, ak = (threadIdx.x & 1) * 8; \
    const int bk = threadIdx.x >> 4, bn0 = (threadIdx.x & 15) * 8; \
    float pra[8], prb[8];

#define GEMM2_LOAD(AEXPR, BEXPR) \
    { _Pragma("unroll") for (int u = 0; u < 8; ++u) { const int kk = k0 + ak + u; pra[u] = (AEXPR); } \
      { const int kk = k0 + bk; \
        _Pragma("unroll") for (int u = 0; u < 8; ++u) { const int nn = bn0 + u; prb[u] = (BEXPR); } } }

#define GEMM2_LOOP(KT, AEXPR, BEXPR) \
    int k0 = 0; \
    GEMM2_LOAD(AEXPR, BEXPR) \
    for (int kt = 0; kt < (KT); ++kt) { \
        __syncthreads(); \
        _Pragma("unroll") for (int u = 0; u < 8; ++u) As[ak + u][am] = pra[u]; \
        _Pragma("unroll") for (int u = 0; u < 8; ++u) Bs[bk][bn0 + u] = prb[u]; \
        __syncthreads(); \
        if (kt + 1 < (KT)) { k0 = (kt + 1) * 16; GEMM2_LOAD(AEXPR, BEXPR) } \
        _Pragma("unroll") \
        for (int k = 0; k < 16; ++k) { \
            float ra[8], rb[8]; \
            *(float4*)&ra[0] = *(const float4*)&As[k][ty8]; \
            *(float4*)&ra[4] = *(const float4*)&As[k][ty8 + 4]; \
            *(float4*)&rb[0] = *(const float4*)&Bs[k][tx4]; \
            *(float4*)&rb[4] = *(const float4*)&Bs[k][64 + tx4]; \
            _Pragma("unroll") for (int i = 0; i < 8; ++i) \
                _Pragma("unroll") for (int j = 0; j < 8; ++j) \
                    acc[i][j] = fmaf(ra[i], rb[j], acc[i][j]); \
        } \
    }

#define EPILOG(...) \
    _Pragma("unroll") for (int i = 0; i < 8; i++) { \
        const int m = row0 + ty8 + i; (void)m; \
        _Pragma("unroll") for (int j = 0; j < 8; j++) { \
            const int n = n0 + ((j < 4) ? (tx4 + j) : (60 + tx4 + j)); \
            const float v = acc[i][j]; \
            __VA_ARGS__ \
        } }

// QKV: [8192,1024] x [1024,3072] -> scatter q/k/v [B,H,T,HS]
__global__ __launch_bounds__(256, 2) void k_qkv() {
    const int row0 = blockIdx.y * 128;
    const int n0 = blockIdx.x * 128;
    GEMM2_PROLOG
    GEMM2_LOOP(64,
               g_xn[(size_t)(row0 + am) * DM + kk],
               g_wqkv[(size_t)kk * 3072 + n0 + nn])
    EPILOG({
        int b = m >> 11;
        int t = m & 2047;
        int hh = n / 192;
        int rr = n % 192;
        int w = rr >> 6;
        int s = rr & 63;
        float* dst = (w == 0) ? g_q : (w == 1) ? g_k : g_v;
        dst[(((size_t)(b * NH + hh)) * TT + t) * HS + s] = v;
    })
}

// out proj + bias + residual
__global__ __launch_bounds__(256, 2) void k_proj(const float* __restrict__ x,
                                                 const float* __restrict__ wo,
                                                 const float* __restrict__ bo) {
    const int row0 = blockIdx.y * 128;
    const int n0 = blockIdx.x * 128;
    GEMM2_PROLOG
    GEMM2_LOOP(64,
               g_att[(size_t)(row0 + am) * DM + kk],
               wo[(size_t)kk * DM + n0 + nn])
    EPILOG({
        g_x1[(size_t)m * DM + n] = v + bo[n] + x[(size_t)m * DM + n];
    })
}

// grouped MoE GEMM: mode 0 -> g_h = xg@w1[e]+b1 ; mode 1 -> g_h *= silu(xg@w2[e]+b2)
__global__ __launch_bounds__(256, 2) void k_moe1(const float* __restrict__ W,
                                                 const float* __restrict__ Bv, int mode) {
    const int row0 = blockIdx.y * 128;
    if (row0 >= g_seg[NE]) return;
    int e = 0;
    while (row0 >= g_seg[e + 1]) e++;
    const float* We = W + (size_t)e * DM * HD;
    const float* Be = Bv + (size_t)e * HD;
    const int n0 = blockIdx.x * 128;
    GEMM2_PROLOG
    GEMM2_LOOP(64,
               g_xg[(size_t)(row0 + am) * DM + kk],
               ((n0 + nn) < HD ? We[(size_t)kk * HD + n0 + nn] : 0.f))
    EPILOG({
        if (n < HD) {
            size_t idx = (size_t)m * HP + n;
            if (mode == 0) {
                g_h[idx] = v + Be[n];
            } else {
                float a = v + Be[n];
                g_h[idx] *= a / (1.f + __expf(-a));
            }
        }
    })
}

// grouped MoE GEMM 2: g_y = g_h @ w3[e] + b3[e]
__global__ __launch_bounds__(256, 2) void k_moe2(const float* __restrict__ W3,
                                                 const float* __restrict__ B3) {
    const int row0 = blockIdx.y * 128;
    if (row0 >= g_seg[NE]) return;
    int e = 0;
    while (row0 >= g_seg[e + 1]) e++;
    const float* We = W3 + (size_t)e * HD * DM;
    const float* Be = B3 + (size_t)e * DM;
    const int n0 = blockIdx.x * 128;
    GEMM2_PROLOG
    GEMM2_LOOP(171,
               (kk < HD ? g_h[(size_t)(row0 + am) * HP + kk] : 0.f),
               (kk < HD ? We[(size_t)kk * DM + n0 + nn] : 0.f))
    EPILOG({
        g_y[(size_t)m * DM + n] = v + Be[n];
    })
}

// ---------------- flash attention (R13 exact; expf kept accurate) ----------------
__global__ void k_attn() {
    extern __shared__ float smf[];
    float(*qs)[68] = (float(*)[68])smf;
    float(*kp)[68] = (float(*)[68])(smf + 64 * 68);
    float(*vs)[68] = (float(*)[68])(smf + 2 * 64 * 68);
    const int qt = blockIdx.x, bh = blockIdx.y;
    const int tid = threadIdx.x;
    const int tx = tid & 15, ty = tid >> 4;
    const size_t base = (size_t)bh * TT * HS;
    const float* qg = g_q + base + (size_t)qt * 64 * HS;
    const float* kg = g_k + base;
    const float* vg = g_v + base;
    {
        int r = tid >> 2, d0 = (tid & 3) * 16;
#pragma unroll
        for (int u = 0; u < 16; u++) qs[r][d0 + u] = qg[r * HS + d0 + u] * 0.125f;
    }
    float acc[4][4] = {};
    float mr[4], lr[4];
#pragma unroll
    for (int i = 0; i < 4; i++) { mr[i] = -INFINITY; lr[i] = 0.f; }

    for (int kt = 0; kt <= qt; ++kt) {
        __syncthreads();
        {
            int r = tid >> 2, d0 = (tid & 3) * 16;
            const float* kk = kg + (size_t)(kt * 64 + r) * HS;
            const float* vv = vg + (size_t)(kt * 64 + r) * HS;
#pragma unroll
            for (int u = 0; u < 16; u++) {
                kp[d0 + u][r] = kk[d0 + u];
                vs[r][d0 + u] = vv[d0 + u];
            }
        }
        __syncthreads();
        float s[4][4] = {};
#pragma unroll 16
        for (int d = 0; d < 64; ++d) {
            float qv[4];
#pragma unroll
            for (int ii = 0; ii < 4; ii++) qv[ii] = qs[ty * 4 + ii][d];
            float4 k4 = *(const float4*)&kp[d][tx * 4];
            float kv[4] = { k4.x, k4.y, k4.z, k4.w };
#pragma unroll
            for (int ii = 0; ii < 4; ii++)
#pragma unroll
                for (int jj = 0; jj < 4; jj++) s[ii][jj] = fmaf(qv[ii], kv[jj], s[ii][jj]);
        }
        if (kt == qt) {
#pragma unroll
            for (int ii = 0; ii < 4; ii++)
#pragma unroll
                for (int jj = 0; jj < 4; jj++)
                    if (tx * 4 + jj > ty * 4 + ii) s[ii][jj] = -INFINITY;
        }
        float mn[4], cor[4];
#pragma unroll
        for (int ii = 0; ii < 4; ii++) {
            float mx = fmaxf(fmaxf(s[ii][0], s[ii][1]), fmaxf(s[ii][2], s[ii][3]));
#pragma unroll
            for (int o = 8; o; o >>= 1) mx = fmaxf(mx, __shfl_xor_sync(0xffffffffu, mx, o));
            mn[ii] = fmaxf(mr[ii], mx);
            cor[ii] = expf(mr[ii] - mn[ii]);
            mr[ii] = mn[ii];
        }
#pragma unroll
        for (int ii = 0; ii < 4; ii++) {
            float su = 0.f;
#pragma unroll
            for (int jj = 0; jj < 4; jj++) { s[ii][jj] = expf(s[ii][jj] - mn[ii]); su += s[ii][jj]; }
#pragma unroll
            for (int o = 8; o; o >>= 1) su += __shfl_xor_sync(0xffffffffu, su, o);
            lr[ii] = lr[ii] * cor[ii] + su;
#pragma unroll
            for (int jj = 0; jj < 4; jj++) acc[ii][jj] *= cor[ii];
        }
        __syncthreads();
#pragma unroll
        for (int ii = 0; ii < 4; ii++)
#pragma unroll
            for (int jj = 0; jj < 4; jj++) kp[ty * 4 + ii][tx * 4 + jj] = s[ii][jj];
        __syncthreads();
#pragma unroll 16
        for (int c = 0; c < 64; ++c) {
            float pv[4];
#pragma unroll
            for (int ii = 0; ii < 4; ii++) pv[ii] = kp[ty * 4 + ii][c];
            float4 v4 = *(const float4*)&vs[c][tx * 4];
            float vv[4] = { v4.x, v4.y, v4.z, v4.w };
#pragma unroll
            for (int ii = 0; ii < 4; ii++)
#pragma unroll
                for (int jj = 0; jj < 4; jj++) acc[ii][jj] = fmaf(pv[ii], vv[jj], acc[ii][jj]);
        }
    }
    int b = bh >> 4, h = bh & 15;
#pragma unroll
    for (int ii = 0; ii < 4; ii++) {
        float inv = 1.f / lr[ii];
#pragma unroll
        for (int jj = 0; jj < 4; jj++) {
            int row = qt * 64 + ty * 4 + ii;
            g_att[((size_t)(b * TT + row)) * DM + h * HS + tx * 4 + jj] = acc[ii][jj] * inv;
        }
    }
}

// ---------------- router / moe routing ----------------
__global__ void k_router(const float* __restrict__ rw, const float* __restrict__ rb) {
    int t = blockIdx.x * 8 + (threadIdx.x >> 5);
    int lane = threadIdx.x & 31;
    const float* xr = g_xn + (size_t)t * DM;
    float a[NE] = {};
    for (int d = lane; d < DM; d += 32) {
        float xv = xr[d];
        const float* w = rw + (size_t)d * NE;
#pragma unroll
        for (int e = 0; e < NE; e++) a[e] += xv * w[e];
    }
#pragma unroll
    for (int e = 0; e < NE; e++)
#pragma unroll
        for (int o = 16; o; o >>= 1) a[e] += __shfl_xor_sync(0xffffffffu, a[e], o);
    if (lane == 0) {
#pragma unroll
        for (int e = 0; e < NE; e++) a[e] += rb[e];
        int e1 = 0; float v1 = a[0];
#pragma unroll
        for (int e = 1; e < NE; e++) if (a[e] > v1) { v1 = a[e]; e1 = e; }
        int e2 = -1; float v2 = -INFINITY;
#pragma unroll
        for (int e = 0; e < NE; e++) if (e != e1 && a[e] > v2) { v2 = a[e]; e2 = e; }
        float w2 = expf(v2 - v1);
        float inv = 1.f / (1.f + w2);
        g_eid[t * 2] = e1; g_eid[t * 2 + 1] = e2;
        g_gate[t * 2] = inv; g_gate[t * 2 + 1] = w2 * inv;
        atomicAdd(&g_count[e1], 1);
        atomicAdd(&g_count[e2], 1);
    }
}

__global__ void k_seg() {
    if (threadIdx.x == 0) {
        int s = 0; g_seg[0] = 0;
        for (int e = 0; e < NE; e++) { s += (g_count[e] + 127) & ~127; g_seg[e + 1] = s; }
    }
}

__global__ void k_fill() {
    int i = blockIdx.x * 256 + threadIdx.x;
    if (i < NSLOT) g_slot_tok[i] = -1;
}

__global__ void k_scatter() {
    int i = blockIdx.x * 256 + threadIdx.x;
    int t = i >> 1;
    int e = g_eid[i];
    int pos = atomicAdd(&g_cursor[e], 1);
    int slot = g_seg[e] + pos;
    g_slot_tok[slot] = t;
    g_tok_slot[i] = slot;
}

__global__ void k_gather() {
    int slot = blockIdx.x;
    int t = g_slot_tok[slot];
    float* dst = g_xg + (size_t)slot * DM;
    if (t >= 0) {
        const float* src = g_xn + (size_t)t * DM;
#pragma unroll
        for (int i = 0; i < 4; i++) dst[threadIdx.x + i * 256] = src[threadIdx.x + i * 256];
    } else {
#pragma unroll
        for (int i = 0; i < 4; i++) dst[threadIdx.x + i * 256] = 0.f;
    }
}

__global__ void k_combine(float* __restrict__ out) {
    int t = blockIdx.x;
    int s0 = g_tok_slot[t * 2], s1 = g_tok_slot[t * 2 + 1];
    float g0 = g_gate[t * 2], g1 = g_gate[t * 2 + 1];
    const float* y0 = g_y + (size_t)s0 * DM;
    const float* y1 = g_y + (size_t)s1 * DM;
    const float* xr = g_x1 + (size_t)t * DM;
    float* o = out + (size_t)t * DM;
#pragma unroll
    for (int i = 0; i < 4; i++) {
        int c = threadIdx.x + i * 256;
        o[c] = xr[c] + g0 * y0[c] + g1 * y1[c];
    }
}

// ---------------- launch ----------------
extern "C" void kernel_launch(void* const* d_in, const int* in_sizes, int n_in,
                              void* d_out, int out_size) {
    const float* x    = (const float*)d_in[0];
    const float* ln1g = (const float*)d_in[1];
    const float* ln1b = (const float*)d_in[2];
    const float* wq   = (const float*)d_in[3];
    const float* wk   = (const float*)d_in[4];
    const float* wv   = (const float*)d_in[5];
    const float* wo   = (const float*)d_in[6];
    const float* bo   = (const float*)d_in[7];
    const float* ln2g = (const float*)d_in[8];
    const float* ln2b = (const float*)d_in[9];
    const float* rw   = (const float*)d_in[10];
    const float* rb   = (const float*)d_in[11];
    const float* w1   = (const float*)d_in[12];
    const float* b1   = (const float*)d_in[13];
    const float* w2   = (const float*)d_in[14];
    const float* b2   = (const float*)d_in[15];
    const float* w3   = (const float*)d_in[16];
    const float* b3   = (const float*)d_in[17];
    float* out = (float*)d_out;

    const int attn_smem = 3 * 64 * 68 * (int)sizeof(float);
    cudaFuncSetAttribute(k_attn, cudaFuncAttributeMaxDynamicSharedMemorySize, attn_smem);

    k_init<<<1, 32>>>();
    k_pack<<<(3 * NH * DM * HS + 255) / 256, 256>>>(wq, wk, wv);
    k_ln<<<TB, 256>>>(x, ln1g, ln1b, 0);
    k_qkv<<<dim3(24, 64), 256>>>();
    k_attn<<<dim3(32, 64), 256, attn_smem>>>();
    k_proj<<<dim3(8, 64), 256>>>(x, wo, bo);
    k_ln<<<TB, 256>>>(x, ln2g, ln2b, 1);
    k_router<<<TB / 8, 256>>>(rw, rb);
    k_seg<<<1, 32>>>();
    k_fill<<<(NSLOT + 255) / 256, 256>>>();
    k_scatter<<<TB * 2 / 256, 256>>>();
    k_gather<<<NSLOT, 256>>>();
    k_moe1<<<dim3(22, NSLOT / 128), 256>>>(w1, b1, 0);
    k_moe1<<<dim3(22, NSLOT / 128), 256>>>(w2, b2, 1);
    k_moe2<<<dim3(8, NSLOT / 128), 256>>>(w3, b3);
    k_combine<<<TB, 256>>>(out);
}

// round 16
// speedup vs baseline: 1.0043x; 1.0025x over previous
#include <cuda_runtime.h>
#include <math.h>
#include <stdint.h>

#define TB 8192        // B*T tokens
#define DM 1024
#define NH 16
#define HS 64
#define TT 2048
#define NE 8
#define HD 2730
#define HP 2732        // padded row stride for hidden
#define NSLOT 17408
#define LNEPS 1e-5f

// ---------------- scratch ----------------
__device__ float g_xn[TB * DM];
__device__ float g_q[TB * DM];
__device__ float g_k[TB * DM];
__device__ float g_v[TB * DM];
__device__ float g_att[TB * DM];
__device__ float g_x1[TB * DM];
__device__ float g_wqkv[DM * 3 * DM];
__device__ int   g_eid[TB * 2];
__device__ float g_gate[TB * 2];
__device__ int   g_count[NE];
__device__ int   g_cursor[NE];
__device__ int   g_seg[NE + 1];
__device__ int   g_slot_tok[NSLOT];
__device__ int   g_tok_slot[TB * 2];
__device__ float g_xg[NSLOT * DM];
__device__ float g_h[(size_t)NSLOT * HP];
__device__ float g_y[NSLOT * DM];

// ---------------- init ----------------
__global__ void k_init() {
    if (threadIdx.x < NE) { g_count[threadIdx.x] = 0; g_cursor[threadIdx.x] = 0; }
}

// ---------------- pack per-head QKV weights into one [D, 3072] matrix ----------------
__global__ void k_pack(const float* __restrict__ wq, const float* __restrict__ wk,
                       const float* __restrict__ wv) {
    int i = blockIdx.x * 256 + threadIdx.x;
    const int per = NH * DM * HS;
    if (i >= 3 * per) return;
    int which = i / per;
    int r = i % per;
    int h = r >> 16;
    int r2 = r & 65535;
    int d = r2 >> 6;
    int s = r2 & 63;
    const float* src = (which == 0) ? wq : (which == 1) ? wk : wv;
    g_wqkv[(size_t)d * 3072 + h * 192 + which * 64 + s] = src[r];
}

// ---------------- layernorm ----------------
__global__ void k_ln(const float* __restrict__ xin, const float* __restrict__ gg,
                     const float* __restrict__ bb, int mode) {
    const float* src = mode ? g_x1 : xin;
    int row = blockIdx.x;
    const float* xr = src + (size_t)row * DM;
    int tid = threadIdx.x;
    float v[4]; float s = 0.f, s2 = 0.f;
#pragma unroll
    for (int i = 0; i < 4; i++) { v[i] = xr[tid + i * 256]; s += v[i]; s2 += v[i] * v[i]; }
#pragma unroll
    for (int o = 16; o; o >>= 1) {
        s  += __shfl_xor_sync(0xffffffffu, s, o);
        s2 += __shfl_xor_sync(0xffffffffu, s2, o);
    }
    __shared__ float ws[8], ws2[8], stat[2];
    int warp = tid >> 5, lane = tid & 31;
    if (lane == 0) { ws[warp] = s; ws2[warp] = s2; }
    __syncthreads();
    if (tid == 0) {
        float ts = 0.f, t2 = 0.f;
        for (int w = 0; w < 8; w++) { ts += ws[w]; t2 += ws2[w]; }
        float mu = ts * (1.f / DM);
        float var = t2 * (1.f / DM) - mu * mu;
        stat[0] = mu; stat[1] = rsqrtf(var + LNEPS);
    }
    __syncthreads();
    float mu = stat[0], inv = stat[1];
    float* outr = g_xn + (size_t)row * DM;
#pragma unroll
    for (int i = 0; i < 4; i++) {
        int c = tid + i * 256;
        outr[c] = (v[i] - mu) * inv * gg[c] + bb[c];
    }
}

// ---------------- FFMA GEMM core (R13 exact): conflict-free B fragments ------------
#define GEMM2_PROLOG \
    __shared__ float As[16][136]; \
    __shared__ float Bs[16][132]; \
    const int tx4 = (threadIdx.x & 15) * 4; \
    const int ty8 = (threadIdx.x >> 4) * 8; \
    float acc[8][8] = {}; \
    const int am = threadIdx.x >> 1, ak = (threadIdx.x & 1) * 8; \
    const int bk = threadIdx.x >> 4, bn0 = (threadIdx.x & 15) * 8; \
    float pra[8], prb[8];

#define GEMM2_LOAD(AEXPR, BEXPR) \
    { _Pragma("unroll") for (int u = 0; u < 8; ++u) { const int kk = k0 + ak + u; pra[u] = (AEXPR); } \
      { const int kk = k0 + bk; \
        _Pragma("unroll") for (int u = 0; u < 8; ++u) { const int nn = bn0 + u; prb[u] = (BEXPR); } } }

#define GEMM2_LOOP(KT, AEXPR, BEXPR) \
    int k0 = 0; \
    GEMM2_LOAD(AEXPR, BEXPR) \
    for (int kt = 0; kt < (KT); ++kt) { \
        __syncthreads(); \
        _Pragma("unroll") for (int u = 0; u < 8; ++u) As[ak + u][am] = pra[u]; \
        _Pragma("unroll") for (int u = 0; u < 8; ++u) Bs[bk][bn0 + u] = prb[u]; \
        __syncthreads(); \
        if (kt + 1 < (KT)) { k0 = (kt + 1) * 16; GEMM2_LOAD(AEXPR, BEXPR) } \
        _Pragma("unroll") \
        for (int k = 0; k < 16; ++k) { \
            float ra[8], rb[8]; \
            *(float4*)&ra[0] = *(const float4*)&As[k][ty8]; \
            *(float4*)&ra[4] = *(const float4*)&As[k][ty8 + 4]; \
            *(float4*)&rb[0] = *(const float4*)&Bs[k][tx4]; \
            *(float4*)&rb[4] = *(const float4*)&Bs[k][64 + tx4]; \
            _Pragma("unroll") for (int i = 0; i < 8; ++i) \
                _Pragma("unroll") for (int j = 0; j < 8; ++j) \
                    acc[i][j] = fmaf(ra[i], rb[j], acc[i][j]); \
        } \
    }

#define EPILOG(...) \
    _Pragma("unroll") for (int i = 0; i < 8; i++) { \
        const int m = row0 + ty8 + i; (void)m; \
        _Pragma("unroll") for (int j = 0; j < 8; j++) { \
            const int n = n0 + ((j < 4) ? (tx4 + j) : (60 + tx4 + j)); \
            const float v = acc[i][j]; \
            __VA_ARGS__ \
        } }

// QKV: [8192,1024] x [1024,3072] -> scatter q/k/v [B,H,T,HS]
__global__ __launch_bounds__(256, 2) void k_qkv() {
    const int row0 = blockIdx.y * 128;
    const int n0 = blockIdx.x * 128;
    GEMM2_PROLOG
    GEMM2_LOOP(64,
               g_xn[(size_t)(row0 + am) * DM + kk],
               g_wqkv[(size_t)kk * 3072 + n0 + nn])
    EPILOG({
        int b = m >> 11;
        int t = m & 2047;
        int hh = n / 192;
        int rr = n % 192;
        int w = rr >> 6;
        int s = rr & 63;
        float* dst = (w == 0) ? g_q : (w == 1) ? g_k : g_v;
        dst[(((size_t)(b * NH + hh)) * TT + t) * HS + s] = v;
    })
}

// out proj + bias + residual
__global__ __launch_bounds__(256, 2) void k_proj(const float* __restrict__ x,
                                                 const float* __restrict__ wo,
                                                 const float* __restrict__ bo) {
    const int row0 = blockIdx.y * 128;
    const int n0 = blockIdx.x * 128;
    GEMM2_PROLOG
    GEMM2_LOOP(64,
               g_att[(size_t)(row0 + am) * DM + kk],
               wo[(size_t)kk * DM + n0 + nn])
    EPILOG({
        g_x1[(size_t)m * DM + n] = v + bo[n] + x[(size_t)m * DM + n];
    })
}

// grouped MoE GEMM: mode 0 -> g_h = xg@w1[e]+b1 ; mode 1 -> g_h *= silu(xg@w2[e]+b2)
__global__ __launch_bounds__(256, 2) void k_moe1(const float* __restrict__ W,
                                                 const float* __restrict__ Bv, int mode) {
    const int row0 = blockIdx.y * 128;
    if (row0 >= g_seg[NE]) return;
    int e = 0;
    while (row0 >= g_seg[e + 1]) e++;
    const float* We = W + (size_t)e * DM * HD;
    const float* Be = Bv + (size_t)e * HD;
    const int n0 = blockIdx.x * 128;
    GEMM2_PROLOG
    GEMM2_LOOP(64,
               g_xg[(size_t)(row0 + am) * DM + kk],
               ((n0 + nn) < HD ? We[(size_t)kk * HD + n0 + nn] : 0.f))
    EPILOG({
        if (n < HD) {
            size_t idx = (size_t)m * HP + n;
            if (mode == 0) {
                g_h[idx] = v + Be[n];
            } else {
                float a = v + Be[n];
                g_h[idx] *= a / (1.f + __expf(-a));
            }
        }
    })
}

// grouped MoE GEMM 2: g_y = g_h @ w3[e] + b3[e]
__global__ __launch_bounds__(256, 2) void k_moe2(const float* __restrict__ W3,
                                                 const float* __restrict__ B3) {
    const int row0 = blockIdx.y * 128;
    if (row0 >= g_seg[NE]) return;
    int e = 0;
    while (row0 >= g_seg[e + 1]) e++;
    const float* We = W3 + (size_t)e * HD * DM;
    const float* Be = B3 + (size_t)e * DM;
    const int n0 = blockIdx.x * 128;
    GEMM2_PROLOG
    GEMM2_LOOP(171,
               (kk < HD ? g_h[(size_t)(row0 + am) * HP + kk] : 0.f),
               (kk < HD ? We[(size_t)kk * DM + n0 + nn] : 0.f))
    EPILOG({
        g_y[(size_t)m * DM + n] = v + Be[n];
    })
}

// ---------------- flash attention: dedicated P buffer (3 syncs/kt) + __expf --------
__global__ void k_attn() {
    extern __shared__ float smf[];
    float(*qs)[68] = (float(*)[68])smf;
    float(*kp)[68] = (float(*)[68])(smf + 64 * 68);
    float(*vs)[68] = (float(*)[68])(smf + 2 * 64 * 68);
    float(*ps)[68] = (float(*)[68])(smf + 3 * 64 * 68);
    const int qt = blockIdx.x, bh = blockIdx.y;
    const int tid = threadIdx.x;
    const int tx = tid & 15, ty = tid >> 4;
    const size_t base = (size_t)bh * TT * HS;
    const float* qg = g_q + base + (size_t)qt * 64 * HS;
    const float* kg = g_k + base;
    const float* vg = g_v + base;
    {
        int r = tid >> 2, d0 = (tid & 3) * 16;
#pragma unroll
        for (int u = 0; u < 16; u++) qs[r][d0 + u] = qg[r * HS + d0 + u] * 0.125f;
    }
    float acc[4][4] = {};
    float mr[4], lr[4];
#pragma unroll
    for (int i = 0; i < 4; i++) { mr[i] = -INFINITY; lr[i] = 0.f; }

    for (int kt = 0; kt <= qt; ++kt) {
        __syncthreads();   // prior iter's QK read of kp and PV read of vs/ps done
        {
            int r = tid >> 2, d0 = (tid & 3) * 16;
            const float* kk = kg + (size_t)(kt * 64 + r) * HS;
            const float* vv = vg + (size_t)(kt * 64 + r) * HS;
#pragma unroll
            for (int u = 0; u < 16; u++) {
                kp[d0 + u][r] = kk[d0 + u];
                vs[r][d0 + u] = vv[d0 + u];
            }
        }
        __syncthreads();   // k/v tiles visible
        float s[4][4] = {};
#pragma unroll 16
        for (int d = 0; d < 64; ++d) {
            float qv[4];
#pragma unroll
            for (int ii = 0; ii < 4; ii++) qv[ii] = qs[ty * 4 + ii][d];
            float4 k4 = *(const float4*)&kp[d][tx * 4];
            float kv[4] = { k4.x, k4.y, k4.z, k4.w };
#pragma unroll
            for (int ii = 0; ii < 4; ii++)
#pragma unroll
                for (int jj = 0; jj < 4; jj++) s[ii][jj] = fmaf(qv[ii], kv[jj], s[ii][jj]);
        }
        if (kt == qt) {
#pragma unroll
            for (int ii = 0; ii < 4; ii++)
#pragma unroll
                for (int jj = 0; jj < 4; jj++)
                    if (tx * 4 + jj > ty * 4 + ii) s[ii][jj] = -INFINITY;
        }
        float mn[4], cor[4];
#pragma unroll
        for (int ii = 0; ii < 4; ii++) {
            float mx = fmaxf(fmaxf(s[ii][0], s[ii][1]), fmaxf(s[ii][2], s[ii][3]));
#pragma unroll
            for (int o = 8; o; o >>= 1) mx = fmaxf(mx, __shfl_xor_sync(0xffffffffu, mx, o));
            mn[ii] = fmaxf(mr[ii], mx);
            cor[ii] = __expf(mr[ii] - mn[ii]);
            mr[ii] = mn[ii];
        }
#pragma unroll
        for (int ii = 0; ii < 4; ii++) {
            float su = 0.f;
#pragma unroll
            for (int jj = 0; jj < 4; jj++) { s[ii][jj] = __expf(s[ii][jj] - mn[ii]); su += s[ii][jj]; }
#pragma unroll
            for (int o = 8; o; o >>= 1) su += __shfl_xor_sync(0xffffffffu, su, o);
            lr[ii] = lr[ii] * cor[ii] + su;
#pragma unroll
            for (int jj = 0; jj < 4; jj++) acc[ii][jj] *= cor[ii];
        }
        // write P to its own buffer (prior PV read of ps guarded by top-of-loop sync)
#pragma unroll
        for (int ii = 0; ii < 4; ii++)
#pragma unroll
            for (int jj = 0; jj < 4; jj++) ps[ty * 4 + ii][tx * 4 + jj] = s[ii][jj];
        __syncthreads();   // ps visible
#pragma unroll 16
        for (int c = 0; c < 64; ++c) {
            float pv[4];
#pragma unroll
            for (int ii = 0; ii < 4; ii++) pv[ii] = ps[ty * 4 + ii][c];
            float4 v4 = *(const float4*)&vs[c][tx * 4];
            float vv[4] = { v4.x, v4.y, v4.z, v4.w };
#pragma unroll
            for (int ii = 0; ii < 4; ii++)
#pragma unroll
                for (int jj = 0; jj < 4; jj++) acc[ii][jj] = fmaf(pv[ii], vv[jj], acc[ii][jj]);
        }
    }
    int b = bh >> 4, h = bh & 15;
#pragma unroll
    for (int ii = 0; ii < 4; ii++) {
        float inv = 1.f / lr[ii];
#pragma unroll
        for (int jj = 0; jj < 4; jj++) {
            int row = qt * 64 + ty * 4 + ii;
            g_att[((size_t)(b * TT + row)) * DM + h * HS + tx * 4 + jj] = acc[ii][jj] * inv;
        }
    }
}

// ---------------- router / moe routing ----------------
__global__ void k_router(const float* __restrict__ rw, const float* __restrict__ rb) {
    int t = blockIdx.x * 8 + (threadIdx.x >> 5);
    int lane = threadIdx.x & 31;
    const float* xr = g_xn + (size_t)t * DM;
    float a[NE] = {};
    for (int d = lane; d < DM; d += 32) {
        float xv = xr[d];
        const float* w = rw + (size_t)d * NE;
#pragma unroll
        for (int e = 0; e < NE; e++) a[e] += xv * w[e];
    }
#pragma unroll
    for (int e = 0; e < NE; e++)
#pragma unroll
        for (int o = 16; o; o >>= 1) a[e] += __shfl_xor_sync(0xffffffffu, a[e], o);
    if (lane == 0) {
#pragma unroll
        for (int e = 0; e < NE; e++) a[e] += rb[e];
        int e1 = 0; float v1 = a[0];
#pragma unroll
        for (int e = 1; e < NE; e++) if (a[e] > v1) { v1 = a[e]; e1 = e; }
        int e2 = -1; float v2 = -INFINITY;
#pragma unroll
        for (int e = 0; e < NE; e++) if (e != e1 && a[e] > v2) { v2 = a[e]; e2 = e; }
        float w2 = expf(v2 - v1);
        float inv = 1.f / (1.f + w2);
        g_eid[t * 2] = e1; g_eid[t * 2 + 1] = e2;
        g_gate[t * 2] = inv; g_gate[t * 2 + 1] = w2 * inv;
        atomicAdd(&g_count[e1], 1);
        atomicAdd(&g_count[e2], 1);
    }
}

__global__ void k_seg() {
    if (threadIdx.x == 0) {
        int s = 0; g_seg[0] = 0;
        for (int e = 0; e < NE; e++) { s += (g_count[e] + 127) & ~127; g_seg[e + 1] = s; }
    }
}

__global__ void k_fill() {
    int i = blockIdx.x * 256 + threadIdx.x;
    if (i < NSLOT) g_slot_tok[i] = -1;
}

__global__ void k_scatter() {
    int i = blockIdx.x * 256 + threadIdx.x;
    int t = i >> 1;
    int e = g_eid[i];
    int pos = atomicAdd(&g_cursor[e], 1);
    int slot = g_seg[e] + pos;
    g_slot_tok[slot] = t;
    g_tok_slot[i] = slot;
}

__global__ void k_gather() {
    int slot = blockIdx.x;
    int t = g_slot_tok[slot];
    float* dst = g_xg + (size_t)slot * DM;
    if (t >= 0) {
        const float* src = g_xn + (size_t)t * DM;
#pragma unroll
        for (int i = 0; i < 4; i++) dst[threadIdx.x + i * 256] = src[threadIdx.x + i * 256];
    } else {
#pragma unroll
        for (int i = 0; i < 4; i++) dst[threadIdx.x + i * 256] = 0.f;
    }
}

__global__ void k_combine(float* __restrict__ out) {
    int t = blockIdx.x;
    int s0 = g_tok_slot[t * 2], s1 = g_tok_slot[t * 2 + 1];
    float g0 = g_gate[t * 2], g1 = g_gate[t * 2 + 1];
    const float* y0 = g_y + (size_t)s0 * DM;
    const float* y1 = g_y + (size_t)s1 * DM;
    const float* xr = g_x1 + (size_t)t * DM;
    float* o = out + (size_t)t * DM;
#pragma unroll
    for (int i = 0; i < 4; i++) {
        int c = threadIdx.x + i * 256;
        o[c] = xr[c] + g0 * y0[c] + g1 * y1[c];
    }
}

// ---------------- launch ----------------
extern "C" void kernel_launch(void* const* d_in, const int* in_sizes, int n_in,
                              void* d_out, int out_size) {
    const float* x    = (const float*)d_in[0];
    const float* ln1g = (const float*)d_in[1];
    const float* ln1b = (const float*)d_in[2];
    const float* wq   = (const float*)d_in[3];
    const float* wk   = (const float*)d_in[4];
    const float* wv   = (const float*)d_in[5];
    const float* wo   = (const float*)d_in[6];
    const float* bo   = (const float*)d_in[7];
    const float* ln2g = (const float*)d_in[8];
    const float* ln2b = (const float*)d_in[9];
    const float* rw   = (const float*)d_in[10];
    const float* rb   = (const float*)d_in[11];
    const float* w1   = (const float*)d_in[12];
    const float* b1   = (const float*)d_in[13];
    const float* w2   = (const float*)d_in[14];
    const float* b2   = (const float*)d_in[15];
    const float* w3   = (const float*)d_in[16];
    const float* b3   = (const float*)d_in[17];
    float* out = (float*)d_out;

    const int attn_smem = 4 * 64 * 68 * (int)sizeof(float);   // 69632 (adds P buffer)
    cudaFuncSetAttribute(k_attn, cudaFuncAttributeMaxDynamicSharedMemorySize, attn_smem);

    k_init<<<1, 32>>>();
    k_pack<<<(3 * NH * DM * HS + 255) / 256, 256>>>(wq, wk, wv);
    k_ln<<<TB, 256>>>(x, ln1g, ln1b, 0);
    k_qkv<<<dim3(24, 64), 256>>>();
    k_attn<<<dim3(32, 64), 256, attn_smem>>>();
    k_proj<<<dim3(8, 64), 256>>>(x, wo, bo);
    k_ln<<<TB, 256>>>(x, ln2g, ln2b, 1);
    k_router<<<TB / 8, 256>>>(rw, rb);
    k_seg<<<1, 32>>>();
    k_fill<<<(NSLOT + 255) / 256, 256>>>();
    k_scatter<<<TB * 2 / 256, 256>>>();
    k_gather<<<NSLOT, 256>>>();
    k_moe1<<<dim3(22, NSLOT / 128), 256>>>(w1, b1, 0);
    k_moe1<<<dim3(22, NSLOT / 128), 256>>>(w2, b2, 1);
    k_moe2<<<dim3(8, NSLOT / 128), 256>>>(w3, b3);
    k_combine<<<TB, 256>>>(out);
}